// round 6
// baseline (speedup 1.0000x reference)
#include <cuda_runtime.h>
#include <cuda_bf16.h>
#include <math.h>
#include <stdint.h>

#define BB   2
#define NQ   1024
#define NKK  2048
#define DIMN 1024
#define NH   16
#define HDIM 64

// ---------------- scratch (static device globals) ---------------------------
__device__ float g_qp[(size_t)BB * NH * NQ * HDIM];    // (B,H,NQ,HD), pre-scaled by 0.125
__device__ float g_kp[(size_t)BB * NH * NKK * HDIM];   // (B,H,NK,HD)
__device__ float g_vp[(size_t)BB * NH * NKK * HDIM];   // (B,H,NK,HD)
__device__ float g_att[(size_t)BB * NQ * NH * HDIM];   // (B,NQ,H*HD)
__device__ float g_gate[(size_t)BB * NQ * NKK];        // gate*valid, 0 if masked (67MB)
__device__ float g_part[BB * 256];
__device__ float g_coef[BB];
__device__ int   g_mask_mode;   // 0=uint8, 1=float32, 2=int32

// bf16 hi/lo planes for emulated-fp32 GEMMs
__device__ __align__(256) __nv_bfloat16 g_qh[(size_t)BB * NQ * DIMN];
__device__ __align__(256) __nv_bfloat16 g_ql[(size_t)BB * NQ * DIMN];
__device__ __align__(256) __nv_bfloat16 g_kh[(size_t)BB * NKK * DIMN];
__device__ __align__(256) __nv_bfloat16 g_kl[(size_t)BB * NKK * DIMN];
__device__ __align__(256) __nv_bfloat16 g_vh[(size_t)BB * NKK * DIMN];
__device__ __align__(256) __nv_bfloat16 g_vl[(size_t)BB * NKK * DIMN];
__device__ __align__(256) __nv_bfloat16 g_ah[(size_t)BB * NQ * DIMN];
__device__ __align__(256) __nv_bfloat16 g_al[(size_t)BB * NQ * DIMN];
__device__ __align__(256) __nv_bfloat16 g_wqh[(size_t)DIMN * DIMN];
__device__ __align__(256) __nv_bfloat16 g_wql[(size_t)DIMN * DIMN];
__device__ __align__(256) __nv_bfloat16 g_wkh[(size_t)DIMN * DIMN];
__device__ __align__(256) __nv_bfloat16 g_wkl[(size_t)DIMN * DIMN];
__device__ __align__(256) __nv_bfloat16 g_wvh[(size_t)DIMN * DIMN];
__device__ __align__(256) __nv_bfloat16 g_wvl[(size_t)DIMN * DIMN];
__device__ __align__(256) __nv_bfloat16 g_woh[(size_t)DIMN * DIMN];
__device__ __align__(256) __nv_bfloat16 g_wol[(size_t)DIMN * DIMN];

// ---------------- mask dtype detection -------------------------------------
__global__ void detect_kernel(const unsigned int* __restrict__ w) {
    __shared__ int hasF, le1;
    if (threadIdx.x == 0) { hasF = 0; le1 = 1; }
    __syncthreads();
    unsigned v = w[threadIdx.x];
    if (v == 0x3F800000u) atomicExch(&hasF, 1);
    if (v > 1u)           atomicExch(&le1, 0);
    __syncthreads();
    if (threadIdx.x == 0) g_mask_mode = hasF ? 1 : (le1 ? 2 : 0);
}

__device__ __forceinline__ bool mget(const void* p, size_t i, int mode) {
    if (mode == 1) return ((const float*)p)[i] != 0.0f;
    if (mode == 2) return ((const int*)p)[i] != 0;
    return ((const unsigned char*)p)[i] != 0;
}

// ---------------- tf32 helpers (attention path) -----------------------------
__device__ __forceinline__ unsigned f2tf(float f) {
    unsigned u;
    asm("cvt.rna.tf32.f32 %0, %1;" : "=r"(u) : "f"(f));
    return u;
}

__device__ __forceinline__ void mma_tf32(float* d, const unsigned* a, const unsigned* b) {
    asm volatile(
        "mma.sync.aligned.m16n8k8.row.col.f32.tf32.tf32.f32 "
        "{%0,%1,%2,%3}, {%4,%5,%6,%7}, {%8,%9}, {%0,%1,%2,%3};"
        : "+f"(d[0]), "+f"(d[1]), "+f"(d[2]), "+f"(d[3])
        : "r"(a[0]), "r"(a[1]), "r"(a[2]), "r"(a[3]), "r"(b[0]), "r"(b[1]));
}

__device__ __forceinline__ void mma_bf16(float* d, const unsigned* a, unsigned b0, unsigned b1) {
    asm volatile(
        "mma.sync.aligned.m16n8k16.row.col.f32.bf16.bf16.f32 "
        "{%0,%1,%2,%3}, {%4,%5,%6,%7}, {%8,%9}, {%0,%1,%2,%3};"
        : "+f"(d[0]), "+f"(d[1]), "+f"(d[2]), "+f"(d[3])
        : "r"(a[0]), "r"(a[1]), "r"(a[2]), "r"(a[3]), "r"(b0), "r"(b1));
}

// ---------------- fp32 -> bf16 hi/lo split ----------------------------------
// dsel: 0 q, 1 k, 2 v, 3 Wq, 4 Wk, 5 Wv, 6 Wo, 7 att(g_att)
__global__ void convert_kernel(const float* __restrict__ srcp, int dsel, int n)
{
    __nv_bfloat16 *hi, *lo;
    switch (dsel) {
        case 0: hi = g_qh;  lo = g_ql;  break;
        case 1: hi = g_kh;  lo = g_kl;  break;
        case 2: hi = g_vh;  lo = g_vl;  break;
        case 3: hi = g_wqh; lo = g_wql; break;
        case 4: hi = g_wkh; lo = g_wkl; break;
        case 5: hi = g_wvh; lo = g_wvl; break;
        case 6: hi = g_woh; lo = g_wol; break;
        default: hi = g_ah; lo = g_al;  break;
    }
    const float* src = (dsel == 7) ? g_att : srcp;
    int i0 = (blockIdx.x * 256 + threadIdx.x) * 4;
    if (i0 >= n) return;
    float4 v = *(const float4*)(src + i0);
    __nv_bfloat16 h0 = __float2bfloat16(v.x);
    __nv_bfloat16 h1 = __float2bfloat16(v.y);
    __nv_bfloat16 h2 = __float2bfloat16(v.z);
    __nv_bfloat16 h3 = __float2bfloat16(v.w);
    __nv_bfloat16 l0 = __float2bfloat16(v.x - __bfloat162float(h0));
    __nv_bfloat16 l1 = __float2bfloat16(v.y - __bfloat162float(h1));
    __nv_bfloat16 l2 = __float2bfloat16(v.z - __bfloat162float(h2));
    __nv_bfloat16 l3 = __float2bfloat16(v.w - __bfloat162float(h3));
    *(__nv_bfloat162*)(hi + i0)     = __nv_bfloat162(h0, h1);
    *(__nv_bfloat162*)(hi + i0 + 2) = __nv_bfloat162(h2, h3);
    *(__nv_bfloat162*)(lo + i0)     = __nv_bfloat162(l0, l1);
    *(__nv_bfloat162*)(lo + i0 + 2) = __nv_bfloat162(l2, l3);
}

// ---------------- bf16x3 GEMM: C = A(MxK) @ W(NxK)^T, K=1024 ----------------
// asel: 0 -> q/Wq -> g_qp (x0.125), 1 -> k/Wk -> g_kp, 2 -> v/Wv -> g_vp,
//       3 -> att/Wo -> Cout (row-masked by kpmq)
// smem: 3 stages x 4 planes(Ah,Al,Bh,Bl) x 128 rows x 16 u32 (32 k-elems).
// chunk swizzle: 16B chunk c stored at c ^ ((row>>1)&3)  -> conflict-free LDS.
#define GK      32
#define GSTAGES 3
#define GPLANE  2048                    // u32 per plane (128*16)
#define GSTAGEU (4 * GPLANE)            // u32 per stage
#define GSMEMU  (GSTAGES * GSTAGEU)     // 24576 u32 = 96 KB

__device__ __forceinline__ int gsw(int r, int p) {
    return r * 16 + ((((p >> 2) ^ ((r >> 1) & 3))) << 2) + (p & 3);
}

__global__ void __launch_bounds__(256, 2) gemm_bf16x3(
    float* __restrict__ Cout, int M, int Nseq, int asel,
    const void* __restrict__ kpmq)
{
    extern __shared__ unsigned smu[];

    const __nv_bfloat16 *Ah, *Al, *Bh, *Bl;
    switch (asel) {
        case 0: Ah = g_qh; Al = g_ql; Bh = g_wqh; Bl = g_wql; break;
        case 1: Ah = g_kh; Al = g_kl; Bh = g_wkh; Bl = g_wkl; break;
        case 2: Ah = g_vh; Al = g_vl; Bh = g_wvh; Bl = g_wvl; break;
        default: Ah = g_ah; Al = g_al; Bh = g_woh; Bl = g_wol; break;
    }

    int tid  = threadIdx.x;
    int lane = tid & 31;
    int warp = tid >> 5;
    int g    = lane >> 2;
    int t4   = lane & 3;
    int wm   = warp >> 2;       // 0..1
    int wn   = warp & 3;        // 0..3
    int row0 = blockIdx.y * 128, col0 = blockIdx.x * 128;

    const __nv_bfloat16* gsrc[4] = {Ah, Al, Bh, Bl};
    const int rbase[4] = {row0, row0, col0, col0};

    // cp.async issue of one stage (k0 = chunk base in K)
    auto issue = [&](int stage, int k0) {
        unsigned sbase = (unsigned)__cvta_generic_to_shared(smu + stage * GSTAGEU);
#pragma unroll
        for (int i = 0; i < 8; i++) {
            int id = i * 256 + tid;          // 0..2047
            int m  = id >> 9;                // plane
            int rc = id & 511;
            int r  = rc >> 2, c = rc & 3;
            const __nv_bfloat16* src = gsrc[m] + (size_t)(rbase[m] + r) * DIMN + k0 + c * 8;
            unsigned dst = sbase + (unsigned)((m * GPLANE + r * 16 + ((c ^ ((r >> 1) & 3)) << 2)) * 4);
            asm volatile("cp.async.cg.shared.global [%0], [%1], 16;\n"
                         :: "r"(dst), "l"(src));
        }
        asm volatile("cp.async.commit_group;\n" ::: "memory");
    };

    float acc[4][4][4];
#pragma unroll
    for (int i = 0; i < 4; i++)
#pragma unroll
        for (int j = 0; j < 4; j++)
#pragma unroll
            for (int c = 0; c < 4; c++) acc[i][j][c] = 0.0f;

    issue(0, 0);
    issue(1, GK);

    const int NIT = DIMN / GK;   // 32
    for (int it = 0; it < NIT; ++it) {
        asm volatile("cp.async.wait_group 1;\n" ::: "memory");
        __syncthreads();
        if (it + 2 < NIT) issue((it + 2) % GSTAGES, (it + 2) * GK);
        else asm volatile("cp.async.commit_group;\n" ::: "memory");

        const unsigned* sAh = smu + (it % GSTAGES) * GSTAGEU;
        const unsigned* sAl = sAh + GPLANE;
        const unsigned* sBh = sAl + GPLANE;
        const unsigned* sBl = sBh + GPLANE;

#pragma unroll
        for (int g16 = 0; g16 < 2; g16++) {
            int p0 = g16 * 8 + t4;
            unsigned ah[4][4], al[4][4];
#pragma unroll
            for (int mi = 0; mi < 4; mi++) {
                int Rb = wm * 64 + mi * 16;
                ah[mi][0] = sAh[gsw(Rb + g,     p0)];
                ah[mi][1] = sAh[gsw(Rb + g + 8, p0)];
                ah[mi][2] = sAh[gsw(Rb + g,     p0 + 4)];
                ah[mi][3] = sAh[gsw(Rb + g + 8, p0 + 4)];
                al[mi][0] = sAl[gsw(Rb + g,     p0)];
                al[mi][1] = sAl[gsw(Rb + g + 8, p0)];
                al[mi][2] = sAl[gsw(Rb + g,     p0 + 4)];
                al[mi][3] = sAl[gsw(Rb + g + 8, p0 + 4)];
            }
#pragma unroll
            for (int nj = 0; nj < 4; nj++) {
                int Cr = wn * 32 + nj * 8 + g;
                unsigned bh0 = sBh[gsw(Cr, p0)];
                unsigned bh1 = sBh[gsw(Cr, p0 + 4)];
                unsigned bl0 = sBl[gsw(Cr, p0)];
                unsigned bl1 = sBl[gsw(Cr, p0 + 4)];
#pragma unroll
                for (int mi = 0; mi < 4; mi++) {
                    mma_bf16(acc[mi][nj], ah[mi], bh0, bh1);   // hi*hi
                    mma_bf16(acc[mi][nj], ah[mi], bl0, bl1);   // hi*lo
                    mma_bf16(acc[mi][nj], al[mi], bh0, bh1);   // lo*hi
                }
            }
        }
    }

    int mode = g_mask_mode;
#pragma unroll
    for (int mi = 0; mi < 4; mi++) {
#pragma unroll
        for (int h2 = 0; h2 < 2; h2++) {
            int r = row0 + wm * 64 + mi * 16 + g + 8 * h2;
            float rowscale = 1.0f;
            if (asel == 3) rowscale = mget(kpmq, (size_t)r, mode) ? 1.0f : 0.0f;
#pragma unroll
            for (int nj = 0; nj < 4; nj++) {
                int c = col0 + wn * 32 + nj * 8 + 2 * t4;
                float v0 = acc[mi][nj][2 * h2];
                float v1 = acc[mi][nj][2 * h2 + 1];
                if (asel == 0) { v0 *= 0.125f; v1 *= 0.125f; }
                if (asel == 3) {
                    Cout[(size_t)r * DIMN + c]     = v0 * rowscale;
                    Cout[(size_t)r * DIMN + c + 1] = v1 * rowscale;
                } else {
                    float* dst = (asel == 0) ? g_qp : ((asel == 1) ? g_kp : g_vp);
                    int bb = r / Nseq, ns = r - bb * Nseq;
                    int hh = c >> 6, hd = c & 63;
                    float* dp = dst + (((size_t)bb * NH + hh) * Nseq + ns) * HDIM + hd;
                    dp[0] = v0; dp[1] = v1;
                }
            }
        }
    }
}

// ---------------- distance mean -> gate coefficient -------------------------
__global__ void mean_stage1(const float* __restrict__ dist,
                            const void* __restrict__ am,
                            const void* __restrict__ kpmk)
{
    int mode = g_mask_mode;
    int b = blockIdx.y;
    size_t base = (size_t)b * NQ * NKK;
    float s = 0.0f;
    for (int i = blockIdx.x * 256 + threadIdx.x; i < NQ * NKK; i += 256 * 256) {
        int kk = i & (NKK - 1);
        if (mget(am, base + i, mode) && mget(kpmk, (size_t)b * NKK + kk, mode))
            s += dist[base + i];
    }
    __shared__ float red[256];
    red[threadIdx.x] = s;
    __syncthreads();
    for (int st = 128; st > 0; st >>= 1) {
        if (threadIdx.x < st) red[threadIdx.x] += red[threadIdx.x + st];
        __syncthreads();
    }
    if (threadIdx.x == 0) g_part[b * 256 + blockIdx.x] = red[0];
}

__global__ void mean_stage2(const float* __restrict__ galpha)
{
    int b = blockIdx.x;
    __shared__ float red[256];
    red[threadIdx.x] = g_part[b * 256 + threadIdx.x];
    __syncthreads();
    for (int st = 128; st > 0; st >>= 1) {
        if (threadIdx.x < st) red[threadIdx.x] += red[threadIdx.x + st];
        __syncthreads();
    }
    if (threadIdx.x == 0) {
        float mean = red[0] / ((float)NQ * (float)NKK + 1e-6f);
        mean = fmaxf(mean, 1e-6f);
        float a = galpha[0];
        float alpha = log1pf(__expf(a));   // softplus
        g_coef[b] = alpha / mean;
    }
}

// ---------------- precompute gate*valid ------------------------------------
__global__ void gate_kernel(const float* __restrict__ dist,
                            const void* __restrict__ am,
                            const void* __restrict__ kpmk)
{
    int mode = g_mask_mode;
    size_t i0 = ((size_t)blockIdx.x * 256 + threadIdx.x) * 4;
    const size_t per_b = (size_t)NQ * NKK;
#pragma unroll
    for (int u = 0; u < 4; u++) {
        size_t i = i0 + u;
        int b = (int)(i / per_b);
        size_t rem = i - (size_t)b * per_b;
        int kk = (int)(rem & (NKK - 1));
        bool valid = mget(am, i, mode) && mget(kpmk, (size_t)b * NKK + kk, mode);
        g_gate[i] = valid ? __expf(-g_coef[b] * dist[i]) : 0.0f;
    }
}

// ---------------- fused flash attention (tf32 mma) --------------------------
// block: 256 thr = 8 warps; q-tile 128 (warp w owns rows w*16..w*16+15); k-tile 64
#define QS_STRIDE 68
#define KS_STRIDE 68
#define VS_STRIDE 72
#define PS_STRIDE 68
#define ATTN_SMEM_UINTS (128*QS_STRIDE + 64*KS_STRIDE + 64*VS_STRIDE + 128*PS_STRIDE)

__device__ __forceinline__ float qmax(float v) {
    v = fmaxf(v, __shfl_xor_sync(0xffffffffu, v, 1));
    v = fmaxf(v, __shfl_xor_sync(0xffffffffu, v, 2));
    return v;
}
__device__ __forceinline__ float qsum(float v) {
    v += __shfl_xor_sync(0xffffffffu, v, 1);
    v += __shfl_xor_sync(0xffffffffu, v, 2);
    return v;
}

__global__ void __launch_bounds__(256, 1) attn_kernel()
{
    extern __shared__ unsigned smu[];
    unsigned* Qs = smu;                                   // [128][68]
    unsigned* Ks = Qs + 128 * QS_STRIDE;                  // [64][68]
    unsigned* Vs = Ks + 64 * KS_STRIDE;                   // [64][72]
    unsigned* Ps = Vs + 64 * VS_STRIDE;                   // [128][68]

    int tid  = threadIdx.x;
    int lane = tid & 31;
    int warp = tid >> 5;
    int g    = lane >> 2;
    int t4   = lane & 3;
    int R    = warp * 16;             // this warp's q rows within tile

    int q0 = blockIdx.x * 128;
    int h  = blockIdx.y, b = blockIdx.z;

    // load Q tile (128x64) -> Qs, tf32
    {
        const float* Qg = g_qp + ((size_t)(b * NH + h) * NQ + q0) * HDIM;
#pragma unroll
        for (int l = 0; l < 8; l++) {
            int idx4 = tid + l * 256;        // over 2048 float4s
            int row = idx4 >> 4, d4 = (idx4 & 15) * 4;
            float4 v = *(const float4*)(Qg + row * HDIM + d4);
            uint4 u = make_uint4(f2tf(v.x), f2tf(v.y), f2tf(v.z), f2tf(v.w));
            *(uint4*)(&Qs[row * QS_STRIDE + d4]) = u;
        }
    }

    float O[8][4];
    float mrow[2] = {-1e30f, -1e30f}, Z2[2] = {0.f, 0.f}, Zg2[2] = {0.f, 0.f};
#pragma unroll
    for (int nj = 0; nj < 8; nj++)
#pragma unroll
        for (int c = 0; c < 4; c++) O[nj][c] = 0.0f;

    const size_t kv_base = (size_t)(b * NH + h) * NKK * HDIM;

    for (int kbase = 0; kbase < NKK; kbase += 64) {
        __syncthreads();   // all warps done with previous Ks/Vs (and Qs stores, iter 0)
        {
            const float* Kg = g_kp + kv_base + (size_t)kbase * HDIM;
            const float* Vg = g_vp + kv_base + (size_t)kbase * HDIM;
#pragma unroll
            for (int l = 0; l < 4; l++) {
                int idx4 = tid + l * 256;    // over 1024 float4s
                int row = idx4 >> 4, d4 = (idx4 & 15) * 4;
                float4 kv = *(const float4*)(Kg + row * HDIM + d4);
                float4 vv = *(const float4*)(Vg + row * HDIM + d4);
                *(uint4*)(&Ks[row * KS_STRIDE + d4]) =
                    make_uint4(f2tf(kv.x), f2tf(kv.y), f2tf(kv.z), f2tf(kv.w));
                *(uint4*)(&Vs[row * VS_STRIDE + d4]) =
                    make_uint4(f2tf(vv.x), f2tf(vv.y), f2tf(vv.z), f2tf(vv.w));
            }
        }
        __syncthreads();

        // ---- S = Q K^T (128x64 tile; this warp: rows R..R+15) ----
        float sfr[8][4];
#pragma unroll
        for (int nj = 0; nj < 8; nj++)
#pragma unroll
            for (int c = 0; c < 4; c++) sfr[nj][c] = 0.0f;

#pragma unroll
        for (int kk = 0; kk < 8; kk++) {
            int kb = kk * 8;
            unsigned afr[4];
            afr[0] = Qs[(R + g) * QS_STRIDE + kb + t4];
            afr[1] = Qs[(R + g + 8) * QS_STRIDE + kb + t4];
            afr[2] = Qs[(R + g) * QS_STRIDE + kb + t4 + 4];
            afr[3] = Qs[(R + g + 8) * QS_STRIDE + kb + t4 + 4];
#pragma unroll
            for (int nj = 0; nj < 8; nj++) {
                unsigned bfr[2];
                bfr[0] = Ks[(nj * 8 + g) * KS_STRIDE + kb + t4];
                bfr[1] = Ks[(nj * 8 + g) * KS_STRIDE + kb + t4 + 4];
                mma_tf32(sfr[nj], afr, bfr);
            }
        }

        // ---- online softmax + gate, per half-row (rows R+g and R+g+8) ----
#pragma unroll
        for (int hf = 0; hf < 2; hf++) {
            int qrow = q0 + R + g + 8 * hf;
            const float* Gp = g_gate + ((size_t)b * NQ + qrow) * NKK + kbase;
            float Gv[16], sv[16];
            float mt = -3.0e38f;
#pragma unroll
            for (int nj = 0; nj < 8; nj++) {
                float2 gg = *(const float2*)(Gp + nj * 8 + 2 * t4);
                Gv[2 * nj] = gg.x; Gv[2 * nj + 1] = gg.y;
                float s0 = (gg.x > 0.f) ? sfr[nj][2 * hf]     : -3.0e38f;
                float s1 = (gg.y > 0.f) ? sfr[nj][2 * hf + 1] : -3.0e38f;
                sv[2 * nj] = s0; sv[2 * nj + 1] = s1;
                mt = fmaxf(mt, fmaxf(s0, s1));
            }
            mt = qmax(mt);
            float mn = fmaxf(mrow[hf], mt);
            float cs = __expf(mrow[hf] - mn);
            mrow[hf] = mn;
            float zl = 0.f, zgl = 0.f;
#pragma unroll
            for (int nj = 0; nj < 8; nj++) {
                float e0 = __expf(sv[2 * nj] - mn);
                float e1 = __expf(sv[2 * nj + 1] - mn);
                float p0 = e0 * Gv[2 * nj];
                float p1 = e1 * Gv[2 * nj + 1];
                zl += e0 + e1; zgl += p0 + p1;
                uint2 pu = make_uint2(f2tf(p0), f2tf(p1));
                *(uint2*)(&Ps[(R + g + 8 * hf) * PS_STRIDE + nj * 8 + 2 * t4]) = pu;
            }
            Z2[hf]  = Z2[hf]  * cs + zl;
            Zg2[hf] = Zg2[hf] * cs + zgl;
#pragma unroll
            for (int nj = 0; nj < 8; nj++) {
                O[nj][2 * hf]     *= cs;
                O[nj][2 * hf + 1] *= cs;
            }
        }
        __syncwarp();   // P rows are warp-private; order STS -> cross-lane LDS

        // ---- O += P @ V ----
#pragma unroll
        for (int kk = 0; kk < 8; kk++) {
            int kb = kk * 8;
            unsigned afr[4];
            afr[0] = Ps[(R + g) * PS_STRIDE + kb + t4];
            afr[1] = Ps[(R + g + 8) * PS_STRIDE + kb + t4];
            afr[2] = Ps[(R + g) * PS_STRIDE + kb + t4 + 4];
            afr[3] = Ps[(R + g + 8) * PS_STRIDE + kb + t4 + 4];
#pragma unroll
            for (int nj = 0; nj < 8; nj++) {
                unsigned bfr[2];
                bfr[0] = Vs[(kb + t4) * VS_STRIDE + nj * 8 + g];
                bfr[1] = Vs[(kb + t4 + 4) * VS_STRIDE + nj * 8 + g];
                mma_tf32(O[nj], afr, bfr);
            }
        }
    }

    // epilogue: out = O / (Zg + 1e-6 * Z) scattered to (B,NQ,H*HD)
#pragma unroll
    for (int hf = 0; hf < 2; hf++) {
        float Zt  = qsum(Z2[hf]);
        float Zgt = qsum(Zg2[hf]);
        float inv = 1.0f / (Zgt + 1e-6f * Zt + 1e-30f);
        int qrow = q0 + R + g + 8 * hf;
        float* outp = g_att + ((size_t)b * NQ + qrow) * (NH * HDIM) + h * HDIM;
#pragma unroll
        for (int nj = 0; nj < 8; nj++) {
            float2 v = make_float2(O[nj][2 * hf] * inv, O[nj][2 * hf + 1] * inv);
            *(float2*)(outp + nj * 8 + 2 * t4) = v;
        }
    }
}

// ---------------- launch -----------------------------------------------------
extern "C" void kernel_launch(void* const* d_in, const int* in_sizes, int n_in,
                              void* d_out, int out_size)
{
    const float* q     = (const float*)d_in[0];
    const float* k     = (const float*)d_in[1];
    const float* v     = (const float*)d_in[2];
    const float* dist  = (const float*)d_in[3];
    const void*  amask = d_in[4];
    const void*  kpmq  = d_in[5];
    const void*  kpmk  = d_in[6];
    const float* ga    = (const float*)d_in[11];
    float* out = (float*)d_out;

    const int attn_smem = ATTN_SMEM_UINTS * (int)sizeof(unsigned);  // ~105.5 KB
    const int gemm_smem = GSMEMU * (int)sizeof(unsigned);           // 96 KB
    cudaFuncSetAttribute(attn_kernel,
                         cudaFuncAttributeMaxDynamicSharedMemorySize, attn_smem);
    cudaFuncSetAttribute(gemm_bf16x3,
                         cudaFuncAttributeMaxDynamicSharedMemorySize, gemm_smem);

    detect_kernel<<<1, 256>>>((const unsigned int*)amask);

    // fp32 -> bf16 hi/lo planes
    const int QE = BB * NQ * DIMN, KE = BB * NKK * DIMN, WE = DIMN * DIMN;
    convert_kernel<<<QE / 1024, 256>>>(q, 0, QE);
    convert_kernel<<<KE / 1024, 256>>>(k, 1, KE);
    convert_kernel<<<KE / 1024, 256>>>(v, 2, KE);
    convert_kernel<<<WE / 1024, 256>>>((const float*)d_in[7], 3, WE);
    convert_kernel<<<WE / 1024, 256>>>((const float*)d_in[8], 4, WE);
    convert_kernel<<<WE / 1024, 256>>>((const float*)d_in[9], 5, WE);
    convert_kernel<<<WE / 1024, 256>>>((const float*)d_in[10], 6, WE);

    gemm_bf16x3<<<dim3(8, 16), 256, gemm_smem>>>(nullptr, BB * NQ,  NQ,  0, nullptr);
    gemm_bf16x3<<<dim3(8, 32), 256, gemm_smem>>>(nullptr, BB * NKK, NKK, 1, nullptr);
    gemm_bf16x3<<<dim3(8, 32), 256, gemm_smem>>>(nullptr, BB * NKK, NKK, 2, nullptr);

    mean_stage1<<<dim3(256, BB), 256>>>(dist, amask, kpmk);
    mean_stage2<<<BB, 256>>>(ga);
    gate_kernel<<<(BB * NQ * NKK) / (256 * 4), 256>>>(dist, amask, kpmk);

    attn_kernel<<<dim3(NQ / 128, NH, BB), 256, attn_smem>>>();

    convert_kernel<<<QE / 1024, 256>>>(nullptr, 7, QE);
    gemm_bf16x3<<<dim3(8, 16), 256, gemm_smem>>>(out, BB * NQ, NQ, 3, kpmq);
}

// round 10
// speedup vs baseline: 1.4485x; 1.4485x over previous
#include <cuda_runtime.h>
#include <cuda_bf16.h>
#include <math.h>
#include <stdint.h>

#define BB   2
#define NQ   1024
#define NKK  2048
#define DIMN 1024
#define NH   16
#define HDIM 64

// ---------------- scratch (static device globals) ---------------------------
__device__ float g_qp[(size_t)BB * NH * NQ * HDIM];    // (B,H,NQ,HD), pre-scaled by 0.125
__device__ float g_kp[(size_t)BB * NH * NKK * HDIM];   // (B,H,NK,HD)
__device__ float g_vp[(size_t)BB * NH * NKK * HDIM];   // (B,H,NK,HD)
__device__ float g_gate[(size_t)BB * NQ * NKK];        // gate*valid, 0 if masked (67MB)
__device__ float g_part[BB * 256];
__device__ float g_coef[BB];
__device__ int   g_mask_mode;   // 0=uint8, 1=float32, 2=int32

// bf16 hi/lo planes for emulated-fp32 GEMMs
__device__ __align__(256) __nv_bfloat16 g_qh[(size_t)BB * NQ * DIMN];
__device__ __align__(256) __nv_bfloat16 g_ql[(size_t)BB * NQ * DIMN];
__device__ __align__(256) __nv_bfloat16 g_kh[(size_t)BB * NKK * DIMN];
__device__ __align__(256) __nv_bfloat16 g_kl[(size_t)BB * NKK * DIMN];
__device__ __align__(256) __nv_bfloat16 g_vh[(size_t)BB * NKK * DIMN];
__device__ __align__(256) __nv_bfloat16 g_vl[(size_t)BB * NKK * DIMN];
__device__ __align__(256) __nv_bfloat16 g_ah[(size_t)BB * NQ * DIMN];   // attn out hi
__device__ __align__(256) __nv_bfloat16 g_al[(size_t)BB * NQ * DIMN];   // attn out lo
__device__ __align__(256) __nv_bfloat16 g_wqh[(size_t)DIMN * DIMN];
__device__ __align__(256) __nv_bfloat16 g_wql[(size_t)DIMN * DIMN];
__device__ __align__(256) __nv_bfloat16 g_wkh[(size_t)DIMN * DIMN];
__device__ __align__(256) __nv_bfloat16 g_wkl[(size_t)DIMN * DIMN];
__device__ __align__(256) __nv_bfloat16 g_wvh[(size_t)DIMN * DIMN];
__device__ __align__(256) __nv_bfloat16 g_wvl[(size_t)DIMN * DIMN];
__device__ __align__(256) __nv_bfloat16 g_woh[(size_t)DIMN * DIMN];
__device__ __align__(256) __nv_bfloat16 g_wol[(size_t)DIMN * DIMN];

// ---------------- mask dtype detection -------------------------------------
__global__ void detect_kernel(const unsigned int* __restrict__ w) {
    __shared__ int hasF, le1;
    if (threadIdx.x == 0) { hasF = 0; le1 = 1; }
    __syncthreads();
    unsigned v = w[threadIdx.x];
    if (v == 0x3F800000u) atomicExch(&hasF, 1);
    if (v > 1u)           atomicExch(&le1, 0);
    __syncthreads();
    if (threadIdx.x == 0) g_mask_mode = hasF ? 1 : (le1 ? 2 : 0);
}

__device__ __forceinline__ bool mget(const void* p, size_t i, int mode) {
    if (mode == 1) return ((const float*)p)[i] != 0.0f;
    if (mode == 2) return ((const int*)p)[i] != 0;
    return ((const unsigned char*)p)[i] != 0;
}

// ---------------- mma helpers ------------------------------------------------
__device__ __forceinline__ unsigned f2tf(float f) {
    unsigned u;
    asm("cvt.rna.tf32.f32 %0, %1;" : "=r"(u) : "f"(f));
    return u;
}

__device__ __forceinline__ void mma_tf32(float* d, const unsigned* a, const unsigned* b) {
    asm volatile(
        "mma.sync.aligned.m16n8k8.row.col.f32.tf32.tf32.f32 "
        "{%0,%1,%2,%3}, {%4,%5,%6,%7}, {%8,%9}, {%0,%1,%2,%3};"
        : "+f"(d[0]), "+f"(d[1]), "+f"(d[2]), "+f"(d[3])
        : "r"(a[0]), "r"(a[1]), "r"(a[2]), "r"(a[3]), "r"(b[0]), "r"(b[1]));
}

__device__ __forceinline__ void mma_bf16(float* d, const unsigned* a, unsigned b0, unsigned b1) {
    asm volatile(
        "mma.sync.aligned.m16n8k16.row.col.f32.bf16.bf16.f32 "
        "{%0,%1,%2,%3}, {%4,%5,%6,%7}, {%8,%9}, {%0,%1,%2,%3};"
        : "+f"(d[0]), "+f"(d[1]), "+f"(d[2]), "+f"(d[3])
        : "r"(a[0]), "r"(a[1]), "r"(a[2]), "r"(a[3]), "r"(b0), "r"(b1));
}

// ---------------- fp32 -> bf16 hi/lo split ----------------------------------
// dsel: 0 q, 1 k, 2 v, 3 Wq, 4 Wk, 5 Wv, 6 Wo
__global__ void convert_kernel(const float* __restrict__ src, int dsel, int n)
{
    __nv_bfloat16 *hi, *lo;
    switch (dsel) {
        case 0: hi = g_qh;  lo = g_ql;  break;
        case 1: hi = g_kh;  lo = g_kl;  break;
        case 2: hi = g_vh;  lo = g_vl;  break;
        case 3: hi = g_wqh; lo = g_wql; break;
        case 4: hi = g_wkh; lo = g_wkl; break;
        case 5: hi = g_wvh; lo = g_wvl; break;
        default: hi = g_woh; lo = g_wol; break;
    }
    int i0 = (blockIdx.x * 256 + threadIdx.x) * 8;
    if (i0 >= n) return;
    float4 va = *(const float4*)(src + i0);
    float4 vb = *(const float4*)(src + i0 + 4);
    float f[8] = {va.x, va.y, va.z, va.w, vb.x, vb.y, vb.z, vb.w};
    __nv_bfloat16 h[8], l[8];
#pragma unroll
    for (int u = 0; u < 8; u++) {
        h[u] = __float2bfloat16(f[u]);
        l[u] = __float2bfloat16(f[u] - __bfloat162float(h[u]));
    }
    *(uint4*)(hi + i0) = *(uint4*)h;
    *(uint4*)(lo + i0) = *(uint4*)l;
}

// ---------------- bf16x3 GEMM: C = A(MxK) @ W(NxK)^T, K=1024 ----------------
// asel: 0 -> q/Wq -> g_qp (x0.125), 1 -> k/Wk -> g_kp, 2 -> v/Wv -> g_vp,
//       3 -> attn-out/Wo -> Cout (row-masked by kpmq)
// smem: 3 stages x 4 planes(Ah,Al,Bh,Bl) x 128 rows x 16 u32 (32 k-elems).
// chunk swizzle: 16B chunk c stored at c ^ ((row>>1)&3)  -> conflict-free LDS.
#define GK      32
#define GSTAGES 3
#define GPLANE  2048                    // u32 per plane (128*16)
#define GSTAGEU (4 * GPLANE)            // u32 per stage
#define GSMEMU  (GSTAGES * GSTAGEU)     // 24576 u32 = 96 KB

__device__ __forceinline__ int gsw(int r, int p) {
    return r * 16 + ((((p >> 2) ^ ((r >> 1) & 3))) << 2) + (p & 3);
}

__global__ void __launch_bounds__(256, 2) gemm_bf16x3(
    float* __restrict__ Cout, int M, int Nseq, int asel,
    const void* __restrict__ kpmq)
{
    extern __shared__ unsigned smu[];

    const __nv_bfloat16 *Ah, *Al, *Bh, *Bl;
    switch (asel) {
        case 0: Ah = g_qh; Al = g_ql; Bh = g_wqh; Bl = g_wql; break;
        case 1: Ah = g_kh; Al = g_kl; Bh = g_wkh; Bl = g_wkl; break;
        case 2: Ah = g_vh; Al = g_vl; Bh = g_wvh; Bl = g_wvl; break;
        default: Ah = g_ah; Al = g_al; Bh = g_woh; Bl = g_wol; break;
    }

    int tid  = threadIdx.x;
    int lane = tid & 31;
    int warp = tid >> 5;
    int g    = lane >> 2;
    int t4   = lane & 3;
    int wm   = warp >> 2;       // 0..1
    int wn   = warp & 3;        // 0..3
    int row0 = blockIdx.y * 128, col0 = blockIdx.x * 128;

    // per-thread fixed cp.async coordinates (plane index is compile-time
    // after unroll: m = i>>1; rc = (i&1)*256 + tid spans 512 chunks/plane)
    int rcA = tid;  // used with i parity

    float acc[4][4][4];
#pragma unroll
    for (int i = 0; i < 4; i++)
#pragma unroll
        for (int j = 0; j < 4; j++)
#pragma unroll
            for (int c = 0; c < 4; c++) acc[i][j][c] = 0.0f;

    auto issue = [&](int stage, int k0) {
        unsigned sbase = (unsigned)__cvta_generic_to_shared(smu + stage * GSTAGEU);
#pragma unroll
        for (int i = 0; i < 8; i++) {
            const int m = i >> 1;                       // compile-time plane
            int rc = (i & 1) * 256 + rcA;               // 0..511
            int r  = rc >> 2, c = rc & 3;
            const __nv_bfloat16* base =
                (m == 0) ? Ah : (m == 1) ? Al : (m == 2) ? Bh : Bl;
            int rb = (m < 2) ? row0 : col0;
            const __nv_bfloat16* src = base + (size_t)(rb + r) * DIMN + k0 + c * 8;
            unsigned dst = sbase +
                (unsigned)((m * GPLANE + r * 16 + ((c ^ ((r >> 1) & 3)) << 2)) * 4);
            asm volatile("cp.async.cg.shared.global [%0], [%1], 16;\n"
                         :: "r"(dst), "l"(src));
        }
        asm volatile("cp.async.commit_group;\n" ::: "memory");
    };

    issue(0, 0);
    issue(1, GK);

    const int NIT = DIMN / GK;   // 32
    for (int it = 0; it < NIT; ++it) {
        asm volatile("cp.async.wait_group 1;\n" ::: "memory");
        __syncthreads();
        if (it + 2 < NIT) issue((it + 2) % GSTAGES, (it + 2) * GK);
        else asm volatile("cp.async.commit_group;\n" ::: "memory");

        const unsigned* sAh = smu + (it % GSTAGES) * GSTAGEU;
        const unsigned* sAl = sAh + GPLANE;
        const unsigned* sBh = sAl + GPLANE;
        const unsigned* sBl = sBh + GPLANE;

#pragma unroll
        for (int g16 = 0; g16 < 2; g16++) {
            int p0 = g16 * 8 + t4;
            // B fragments for all 4 nj: 16 regs
            unsigned bh[4][2], bl[4][2];
#pragma unroll
            for (int nj = 0; nj < 4; nj++) {
                int Cr = wn * 32 + nj * 8 + g;
                bh[nj][0] = sBh[gsw(Cr, p0)];
                bh[nj][1] = sBh[gsw(Cr, p0 + 4)];
                bl[nj][0] = sBl[gsw(Cr, p0)];
                bl[nj][1] = sBl[gsw(Cr, p0 + 4)];
            }
            // stream A fragments per mi (8 regs live)
#pragma unroll
            for (int mi = 0; mi < 4; mi++) {
                int Rb = wm * 64 + mi * 16;
                unsigned ah[4], al[4];
                ah[0] = sAh[gsw(Rb + g,     p0)];
                ah[1] = sAh[gsw(Rb + g + 8, p0)];
                ah[2] = sAh[gsw(Rb + g,     p0 + 4)];
                ah[3] = sAh[gsw(Rb + g + 8, p0 + 4)];
                al[0] = sAl[gsw(Rb + g,     p0)];
                al[1] = sAl[gsw(Rb + g + 8, p0)];
                al[2] = sAl[gsw(Rb + g,     p0 + 4)];
                al[3] = sAl[gsw(Rb + g + 8, p0 + 4)];
#pragma unroll
                for (int nj = 0; nj < 4; nj++) {
                    mma_bf16(acc[mi][nj], ah, bh[nj][0], bh[nj][1]);   // hi*hi
                    mma_bf16(acc[mi][nj], ah, bl[nj][0], bl[nj][1]);   // hi*lo
                    mma_bf16(acc[mi][nj], al, bh[nj][0], bh[nj][1]);   // lo*hi
                }
            }
        }
    }

    int mode = g_mask_mode;
#pragma unroll
    for (int mi = 0; mi < 4; mi++) {
#pragma unroll
        for (int h2 = 0; h2 < 2; h2++) {
            int r = row0 + wm * 64 + mi * 16 + g + 8 * h2;
            float rowscale = 1.0f;
            if (asel == 3) rowscale = mget(kpmq, (size_t)r, mode) ? 1.0f : 0.0f;
#pragma unroll
            for (int nj = 0; nj < 4; nj++) {
                int c = col0 + wn * 32 + nj * 8 + 2 * t4;
                float v0 = acc[mi][nj][2 * h2];
                float v1 = acc[mi][nj][2 * h2 + 1];
                if (asel == 0) { v0 *= 0.125f; v1 *= 0.125f; }
                if (asel == 3) {
                    Cout[(size_t)r * DIMN + c]     = v0 * rowscale;
                    Cout[(size_t)r * DIMN + c + 1] = v1 * rowscale;
                } else {
                    float* dst = (asel == 0) ? g_qp : ((asel == 1) ? g_kp : g_vp);
                    int bb = r / Nseq, ns = r - bb * Nseq;
                    int hh = c >> 6, hd = c & 63;
                    float* dp = dst + (((size_t)bb * NH + hh) * Nseq + ns) * HDIM + hd;
                    dp[0] = v0; dp[1] = v1;
                }
            }
        }
    }
}

// ---------------- distance mean -> gate coefficient -------------------------
__global__ void mean_stage1(const float* __restrict__ dist,
                            const void* __restrict__ am,
                            const void* __restrict__ kpmk)
{
    int mode = g_mask_mode;
    int b = blockIdx.y;
    size_t base = (size_t)b * NQ * NKK;
    float s = 0.0f;
    for (int i = blockIdx.x * 256 + threadIdx.x; i < NQ * NKK; i += 256 * 256) {
        int kk = i & (NKK - 1);
        if (mget(am, base + i, mode) && mget(kpmk, (size_t)b * NKK + kk, mode))
            s += dist[base + i];
    }
    __shared__ float red[256];
    red[threadIdx.x] = s;
    __syncthreads();
    for (int st = 128; st > 0; st >>= 1) {
        if (threadIdx.x < st) red[threadIdx.x] += red[threadIdx.x + st];
        __syncthreads();
    }
    if (threadIdx.x == 0) g_part[b * 256 + blockIdx.x] = red[0];
}

__global__ void mean_stage2(const float* __restrict__ galpha)
{
    int b = blockIdx.x;
    __shared__ float red[256];
    red[threadIdx.x] = g_part[b * 256 + threadIdx.x];
    __syncthreads();
    for (int st = 128; st > 0; st >>= 1) {
        if (threadIdx.x < st) red[threadIdx.x] += red[threadIdx.x + st];
        __syncthreads();
    }
    if (threadIdx.x == 0) {
        float mean = red[0] / ((float)NQ * (float)NKK + 1e-6f);
        mean = fmaxf(mean, 1e-6f);
        float a = galpha[0];
        float alpha = log1pf(__expf(a));   // softplus
        g_coef[b] = alpha / mean;
    }
}

// ---------------- precompute gate*valid ------------------------------------
__global__ void gate_kernel(const float* __restrict__ dist,
                            const void* __restrict__ am,
                            const void* __restrict__ kpmk)
{
    int mode = g_mask_mode;
    size_t i0 = ((size_t)blockIdx.x * 256 + threadIdx.x) * 4;
    const size_t per_b = (size_t)NQ * NKK;
#pragma unroll
    for (int u = 0; u < 4; u++) {
        size_t i = i0 + u;
        int b = (int)(i / per_b);
        size_t rem = i - (size_t)b * per_b;
        int kk = (int)(rem & (NKK - 1));
        bool valid = mget(am, i, mode) && mget(kpmk, (size_t)b * NKK + kk, mode);
        g_gate[i] = valid ? __expf(-g_coef[b] * dist[i]) : 0.0f;
    }
}

// ---------------- fused flash attention (tf32 mma) --------------------------
// block: 256 thr = 8 warps; q-tile 128 (warp w owns rows w*16..w*16+15); k-tile 64
#define QS_STRIDE 68
#define KS_STRIDE 68
#define VS_STRIDE 72
#define PS_STRIDE 68
#define ATTN_SMEM_UINTS (128*QS_STRIDE + 64*KS_STRIDE + 64*VS_STRIDE + 128*PS_STRIDE)

__device__ __forceinline__ float qmax(float v) {
    v = fmaxf(v, __shfl_xor_sync(0xffffffffu, v, 1));
    v = fmaxf(v, __shfl_xor_sync(0xffffffffu, v, 2));
    return v;
}
__device__ __forceinline__ float qsum(float v) {
    v += __shfl_xor_sync(0xffffffffu, v, 1);
    v += __shfl_xor_sync(0xffffffffu, v, 2);
    return v;
}

__global__ void __launch_bounds__(256, 1) attn_kernel()
{
    extern __shared__ unsigned smu[];
    unsigned* Qs = smu;                                   // [128][68]
    unsigned* Ks = Qs + 128 * QS_STRIDE;                  // [64][68]
    unsigned* Vs = Ks + 64 * KS_STRIDE;                   // [64][72]
    unsigned* Ps = Vs + 64 * VS_STRIDE;                   // [128][68]

    int tid  = threadIdx.x;
    int lane = tid & 31;
    int warp = tid >> 5;
    int g    = lane >> 2;
    int t4   = lane & 3;
    int R    = warp * 16;             // this warp's q rows within tile

    int q0 = blockIdx.x * 128;
    int h  = blockIdx.y, b = blockIdx.z;

    // load Q tile (128x64) -> Qs, tf32
    {
        const float* Qg = g_qp + ((size_t)(b * NH + h) * NQ + q0) * HDIM;
#pragma unroll
        for (int l = 0; l < 8; l++) {
            int idx4 = tid + l * 256;        // over 2048 float4s
            int row = idx4 >> 4, d4 = (idx4 & 15) * 4;
            float4 v = *(const float4*)(Qg + row * HDIM + d4);
            uint4 u = make_uint4(f2tf(v.x), f2tf(v.y), f2tf(v.z), f2tf(v.w));
            *(uint4*)(&Qs[row * QS_STRIDE + d4]) = u;
        }
    }

    float O[8][4];
    float mrow[2] = {-1e30f, -1e30f}, Z2[2] = {0.f, 0.f}, Zg2[2] = {0.f, 0.f};
#pragma unroll
    for (int nj = 0; nj < 8; nj++)
#pragma unroll
        for (int c = 0; c < 4; c++) O[nj][c] = 0.0f;

    const size_t kv_base = (size_t)(b * NH + h) * NKK * HDIM;

    for (int kbase = 0; kbase < NKK; kbase += 64) {
        __syncthreads();   // all warps done with previous Ks/Vs (and Qs stores, iter 0)
        {
            const float* Kg = g_kp + kv_base + (size_t)kbase * HDIM;
            const float* Vg = g_vp + kv_base + (size_t)kbase * HDIM;
#pragma unroll
            for (int l = 0; l < 4; l++) {
                int idx4 = tid + l * 256;    // over 1024 float4s
                int row = idx4 >> 4, d4 = (idx4 & 15) * 4;
                float4 kv = *(const float4*)(Kg + row * HDIM + d4);
                float4 vv = *(const float4*)(Vg + row * HDIM + d4);
                *(uint4*)(&Ks[row * KS_STRIDE + d4]) =
                    make_uint4(f2tf(kv.x), f2tf(kv.y), f2tf(kv.z), f2tf(kv.w));
                *(uint4*)(&Vs[row * VS_STRIDE + d4]) =
                    make_uint4(f2tf(vv.x), f2tf(vv.y), f2tf(vv.z), f2tf(vv.w));
            }
        }
        __syncthreads();

        // ---- S = Q K^T (128x64 tile; this warp: rows R..R+15) ----
        float sfr[8][4];
#pragma unroll
        for (int nj = 0; nj < 8; nj++)
#pragma unroll
            for (int c = 0; c < 4; c++) sfr[nj][c] = 0.0f;

#pragma unroll
        for (int kk = 0; kk < 8; kk++) {
            int kb = kk * 8;
            unsigned afr[4];
            afr[0] = Qs[(R + g) * QS_STRIDE + kb + t4];
            afr[1] = Qs[(R + g + 8) * QS_STRIDE + kb + t4];
            afr[2] = Qs[(R + g) * QS_STRIDE + kb + t4 + 4];
            afr[3] = Qs[(R + g + 8) * QS_STRIDE + kb + t4 + 4];
#pragma unroll
            for (int nj = 0; nj < 8; nj++) {
                unsigned bfr[2];
                bfr[0] = Ks[(nj * 8 + g) * KS_STRIDE + kb + t4];
                bfr[1] = Ks[(nj * 8 + g) * KS_STRIDE + kb + t4 + 4];
                mma_tf32(sfr[nj], afr, bfr);
            }
        }

        // ---- online softmax + gate, per half-row (rows R+g and R+g+8) ----
#pragma unroll
        for (int hf = 0; hf < 2; hf++) {
            int qrow = q0 + R + g + 8 * hf;
            const float* Gp = g_gate + ((size_t)b * NQ + qrow) * NKK + kbase;
            float Gv[16], sv[16];
            float mt = -3.0e38f;
#pragma unroll
            for (int nj = 0; nj < 8; nj++) {
                float2 gg = *(const float2*)(Gp + nj * 8 + 2 * t4);
                Gv[2 * nj] = gg.x; Gv[2 * nj + 1] = gg.y;
                float s0 = (gg.x > 0.f) ? sfr[nj][2 * hf]     : -3.0e38f;
                float s1 = (gg.y > 0.f) ? sfr[nj][2 * hf + 1] : -3.0e38f;
                sv[2 * nj] = s0; sv[2 * nj + 1] = s1;
                mt = fmaxf(mt, fmaxf(s0, s1));
            }
            mt = qmax(mt);
            float mn = fmaxf(mrow[hf], mt);
            float cs = __expf(mrow[hf] - mn);
            mrow[hf] = mn;
            float zl = 0.f, zgl = 0.f;
#pragma unroll
            for (int nj = 0; nj < 8; nj++) {
                float e0 = __expf(sv[2 * nj] - mn);
                float e1 = __expf(sv[2 * nj + 1] - mn);
                float p0 = e0 * Gv[2 * nj];
                float p1 = e1 * Gv[2 * nj + 1];
                zl += e0 + e1; zgl += p0 + p1;
                uint2 pu = make_uint2(f2tf(p0), f2tf(p1));
                *(uint2*)(&Ps[(R + g + 8 * hf) * PS_STRIDE + nj * 8 + 2 * t4]) = pu;
            }
            Z2[hf]  = Z2[hf]  * cs + zl;
            Zg2[hf] = Zg2[hf] * cs + zgl;
#pragma unroll
            for (int nj = 0; nj < 8; nj++) {
                O[nj][2 * hf]     *= cs;
                O[nj][2 * hf + 1] *= cs;
            }
        }
        __syncwarp();   // P rows are warp-private; order STS -> cross-lane LDS

        // ---- O += P @ V ----
#pragma unroll
        for (int kk = 0; kk < 8; kk++) {
            int kb = kk * 8;
            unsigned afr[4];
            afr[0] = Ps[(R + g) * PS_STRIDE + kb + t4];
            afr[1] = Ps[(R + g + 8) * PS_STRIDE + kb + t4];
            afr[2] = Ps[(R + g) * PS_STRIDE + kb + t4 + 4];
            afr[3] = Ps[(R + g + 8) * PS_STRIDE + kb + t4 + 4];
#pragma unroll
            for (int nj = 0; nj < 8; nj++) {
                unsigned bfr[2];
                bfr[0] = Vs[(kb + t4) * VS_STRIDE + nj * 8 + g];
                bfr[1] = Vs[(kb + t4 + 4) * VS_STRIDE + nj * 8 + g];
                mma_tf32(O[nj], afr, bfr);
            }
        }
    }

    // epilogue: out = O / (Zg + 1e-6*Z), write bf16 hi/lo planes directly
#pragma unroll
    for (int hf = 0; hf < 2; hf++) {
        float Zt  = qsum(Z2[hf]);
        float Zgt = qsum(Zg2[hf]);
        float inv = 1.0f / (Zgt + 1e-6f * Zt + 1e-30f);
        int qrow = q0 + R + g + 8 * hf;
        size_t obase = ((size_t)b * NQ + qrow) * (NH * HDIM) + h * HDIM;
#pragma unroll
        for (int nj = 0; nj < 8; nj++) {
            float v0 = O[nj][2 * hf] * inv;
            float v1 = O[nj][2 * hf + 1] * inv;
            __nv_bfloat16 h0 = __float2bfloat16(v0);
            __nv_bfloat16 h1 = __float2bfloat16(v1);
            __nv_bfloat16 l0 = __float2bfloat16(v0 - __bfloat162float(h0));
            __nv_bfloat16 l1 = __float2bfloat16(v1 - __bfloat162float(h1));
            size_t off = obase + nj * 8 + 2 * t4;
            *(__nv_bfloat162*)(g_ah + off) = __nv_bfloat162(h0, h1);
            *(__nv_bfloat162*)(g_al + off) = __nv_bfloat162(l0, l1);
        }
    }
}

// ---------------- launch -----------------------------------------------------
extern "C" void kernel_launch(void* const* d_in, const int* in_sizes, int n_in,
                              void* d_out, int out_size)
{
    const float* q     = (const float*)d_in[0];
    const float* k     = (const float*)d_in[1];
    const float* v     = (const float*)d_in[2];
    const float* dist  = (const float*)d_in[3];
    const void*  amask = d_in[4];
    const void*  kpmq  = d_in[5];
    const void*  kpmk  = d_in[6];
    const float* ga    = (const float*)d_in[11];
    float* out = (float*)d_out;

    const int attn_smem = ATTN_SMEM_UINTS * (int)sizeof(unsigned);  // ~105.5 KB
    const int gemm_smem = GSMEMU * (int)sizeof(unsigned);           // 96 KB
    cudaFuncSetAttribute(attn_kernel,
                         cudaFuncAttributeMaxDynamicSharedMemorySize, attn_smem);
    cudaFuncSetAttribute(gemm_bf16x3,
                         cudaFuncAttributeMaxDynamicSharedMemorySize, gemm_smem);

    detect_kernel<<<1, 256>>>((const unsigned int*)amask);

    // fp32 -> bf16 hi/lo planes (8 elems/thread)
    const int QE = BB * NQ * DIMN, KE = BB * NKK * DIMN, WE = DIMN * DIMN;
    convert_kernel<<<QE / 2048, 256>>>(q, 0, QE);
    convert_kernel<<<KE / 2048, 256>>>(k, 1, KE);
    convert_kernel<<<KE / 2048, 256>>>(v, 2, KE);
    convert_kernel<<<WE / 2048, 256>>>((const float*)d_in[7], 3, WE);
    convert_kernel<<<WE / 2048, 256>>>((const float*)d_in[8], 4, WE);
    convert_kernel<<<WE / 2048, 256>>>((const float*)d_in[9], 5, WE);
    convert_kernel<<<WE / 2048, 256>>>((const float*)d_in[10], 6, WE);

    gemm_bf16x3<<<dim3(8, 16), 256, gemm_smem>>>(nullptr, BB * NQ,  NQ,  0, nullptr);
    gemm_bf16x3<<<dim3(8, 32), 256, gemm_smem>>>(nullptr, BB * NKK, NKK, 1, nullptr);
    gemm_bf16x3<<<dim3(8, 32), 256, gemm_smem>>>(nullptr, BB * NKK, NKK, 2, nullptr);

    mean_stage1<<<dim3(256, BB), 256>>>(dist, amask, kpmk);
    mean_stage2<<<BB, 256>>>(ga);
    gate_kernel<<<(BB * NQ * NKK) / (256 * 4), 256>>>(dist, amask, kpmk);

    attn_kernel<<<dim3(NQ / 128, NH, BB), 256, attn_smem>>>();

    gemm_bf16x3<<<dim3(8, 16), 256, gemm_smem>>>(out, BB * NQ, NQ, 3, kpmq);
}

// round 15
// speedup vs baseline: 1.6229x; 1.1204x over previous
#include <cuda_runtime.h>
#include <cuda_bf16.h>
#include <math.h>
#include <stdint.h>

#define BB   2
#define NQ   1024
#define NKK  2048
#define DIMN 1024
#define NH   16
#define HDIM 64

// ---------------- scratch (static device globals) ---------------------------
__device__ float g_qp[(size_t)BB * NH * NQ * HDIM];    // (B,H,NQ,HD), pre-scaled by 0.125
__device__ float g_kp[(size_t)BB * NH * NKK * HDIM];   // (B,H,NK,HD)
__device__ float g_vp[(size_t)BB * NH * NKK * HDIM];   // (B,H,NK,HD)
__device__ float g_gate[(size_t)BB * NQ * NKK];        // gate*valid, 0 if masked
__device__ float g_part[BB * 256];
__device__ float g_coef[BB];
__device__ int   g_mask_mode;   // 0=uint8, 1=float32, 2=int32

// bf16 hi/lo planes for emulated-fp32 GEMMs
__device__ __align__(256) __nv_bfloat16 g_qh[(size_t)BB * NQ * DIMN];
__device__ __align__(256) __nv_bfloat16 g_ql[(size_t)BB * NQ * DIMN];
__device__ __align__(256) __nv_bfloat16 g_kh[(size_t)BB * NKK * DIMN];
__device__ __align__(256) __nv_bfloat16 g_kl[(size_t)BB * NKK * DIMN];
__device__ __align__(256) __nv_bfloat16 g_vh[(size_t)BB * NKK * DIMN];
__device__ __align__(256) __nv_bfloat16 g_vl[(size_t)BB * NKK * DIMN];
__device__ __align__(256) __nv_bfloat16 g_ah[(size_t)BB * NQ * DIMN];   // attn out hi
__device__ __align__(256) __nv_bfloat16 g_al[(size_t)BB * NQ * DIMN];   // attn out lo
__device__ __align__(256) __nv_bfloat16 g_wqh[(size_t)DIMN * DIMN];
__device__ __align__(256) __nv_bfloat16 g_wql[(size_t)DIMN * DIMN];
__device__ __align__(256) __nv_bfloat16 g_wkh[(size_t)DIMN * DIMN];
__device__ __align__(256) __nv_bfloat16 g_wkl[(size_t)DIMN * DIMN];
__device__ __align__(256) __nv_bfloat16 g_wvh[(size_t)DIMN * DIMN];
__device__ __align__(256) __nv_bfloat16 g_wvl[(size_t)DIMN * DIMN];
__device__ __align__(256) __nv_bfloat16 g_woh[(size_t)DIMN * DIMN];
__device__ __align__(256) __nv_bfloat16 g_wol[(size_t)DIMN * DIMN];

// ---------------- mask dtype detection -------------------------------------
__global__ void detect_kernel(const unsigned int* __restrict__ w) {
    __shared__ int hasF, le1;
    if (threadIdx.x == 0) { hasF = 0; le1 = 1; }
    __syncthreads();
    unsigned v = w[threadIdx.x];
    if (v == 0x3F800000u) atomicExch(&hasF, 1);
    if (v > 1u)           atomicExch(&le1, 0);
    __syncthreads();
    if (threadIdx.x == 0) g_mask_mode = hasF ? 1 : (le1 ? 2 : 0);
}

__device__ __forceinline__ bool mget(const void* p, size_t i, int mode) {
    if (mode == 1) return ((const float*)p)[i] != 0.0f;
    if (mode == 2) return ((const int*)p)[i] != 0;
    return ((const unsigned char*)p)[i] != 0;
}

// ---------------- mma helpers ------------------------------------------------
__device__ __forceinline__ unsigned f2tf(float f) {
    unsigned u;
    asm("cvt.rna.tf32.f32 %0, %1;" : "=r"(u) : "f"(f));
    return u;
}

__device__ __forceinline__ void mma_tf32(float* d, const unsigned* a, const unsigned* b) {
    asm volatile(
        "mma.sync.aligned.m16n8k8.row.col.f32.tf32.tf32.f32 "
        "{%0,%1,%2,%3}, {%4,%5,%6,%7}, {%8,%9}, {%0,%1,%2,%3};"
        : "+f"(d[0]), "+f"(d[1]), "+f"(d[2]), "+f"(d[3])
        : "r"(a[0]), "r"(a[1]), "r"(a[2]), "r"(a[3]), "r"(b[0]), "r"(b[1]));
}

__device__ __forceinline__ void mma_bf16(float* d, const unsigned* a, unsigned b0, unsigned b1) {
    asm volatile(
        "mma.sync.aligned.m16n8k16.row.col.f32.bf16.bf16.f32 "
        "{%0,%1,%2,%3}, {%4,%5,%6,%7}, {%8,%9}, {%0,%1,%2,%3};"
        : "+f"(d[0]), "+f"(d[1]), "+f"(d[2]), "+f"(d[3])
        : "r"(a[0]), "r"(a[1]), "r"(a[2]), "r"(a[3]), "r"(b0), "r"(b1));
}

// ---------------- fp32 -> bf16 hi/lo split (ALL inputs, one launch) ----------
// blocks: [0,1024) q | [1024,3072) k | [3072,5120) v |
//         [5120,5632) Wq | [5632,6144) Wk | [6144,6656) Wv | [6656,7168) Wo
__global__ void convert_all(const float* __restrict__ q, const float* __restrict__ k,
                            const float* __restrict__ v, const float* __restrict__ wq,
                            const float* __restrict__ wk, const float* __restrict__ wv,
                            const float* __restrict__ wo)
{
    int blk = blockIdx.x;
    const float* src; __nv_bfloat16 *hi, *lo; int lb;
    if (blk < 1024)      { src = q;  hi = g_qh;  lo = g_ql;  lb = blk; }
    else if (blk < 3072) { src = k;  hi = g_kh;  lo = g_kl;  lb = blk - 1024; }
    else if (blk < 5120) { src = v;  hi = g_vh;  lo = g_vl;  lb = blk - 3072; }
    else if (blk < 5632) { src = wq; hi = g_wqh; lo = g_wql; lb = blk - 5120; }
    else if (blk < 6144) { src = wk; hi = g_wkh; lo = g_wkl; lb = blk - 5632; }
    else if (blk < 6656) { src = wv; hi = g_wvh; lo = g_wvl; lb = blk - 6144; }
    else                 { src = wo; hi = g_woh; lo = g_wol; lb = blk - 6656; }

    int i0 = (lb * 256 + threadIdx.x) * 8;
    float4 va = *(const float4*)(src + i0);
    float4 vb = *(const float4*)(src + i0 + 4);
    float f[8] = {va.x, va.y, va.z, va.w, vb.x, vb.y, vb.z, vb.w};
    __nv_bfloat16 h[8], l[8];
#pragma unroll
    for (int u = 0; u < 8; u++) {
        h[u] = __float2bfloat16(f[u]);
        l[u] = __float2bfloat16(f[u] - __bfloat162float(h[u]));
    }
    *(uint4*)(hi + i0) = *(uint4*)h;
    *(uint4*)(lo + i0) = *(uint4*)l;
}

// ---------------- bf16x3 GEMM: C = A(MxK) @ W(NxK)^T, K=1024 ----------------
// aselp: -1 -> fused QKV dispatch on blockIdx.y (16 Q-blocks, 32 K, 32 V)
//         3 -> attn-out/Wo -> Cout (row-masked by kpmq)
#define GK      32
#define GSTAGES 3
#define GPLANE  2048                    // u32 per plane (128*16)
#define GSTAGEU (4 * GPLANE)            // u32 per stage
#define GSMEMU  (GSTAGES * GSTAGEU)     // 24576 u32 = 96 KB

__device__ __forceinline__ int gsw(int r, int p) {
    return r * 16 + ((((p >> 2) ^ ((r >> 1) & 3))) << 2) + (p & 3);
}

__global__ void __launch_bounds__(256, 2) gemm_bf16x3(
    float* __restrict__ Cout, int aselp, const void* __restrict__ kpmq)
{
    extern __shared__ unsigned smu[];

    int by = blockIdx.y;
    int asel, row0, Nseq;
    if (aselp == -1) {
        if (by < 16)      { asel = 0; row0 = by * 128;        Nseq = NQ;  }
        else if (by < 48) { asel = 1; row0 = (by - 16) * 128; Nseq = NKK; }
        else              { asel = 2; row0 = (by - 48) * 128; Nseq = NKK; }
    } else { asel = 3; row0 = by * 128; Nseq = NQ; }

    const __nv_bfloat16 *Ah, *Al, *Bh, *Bl;
    switch (asel) {
        case 0: Ah = g_qh; Al = g_ql; Bh = g_wqh; Bl = g_wql; break;
        case 1: Ah = g_kh; Al = g_kl; Bh = g_wkh; Bl = g_wkl; break;
        case 2: Ah = g_vh; Al = g_vl; Bh = g_wvh; Bl = g_wvl; break;
        default: Ah = g_ah; Al = g_al; Bh = g_woh; Bl = g_wol; break;
    }

    int tid  = threadIdx.x;
    int lane = tid & 31;
    int warp = tid >> 5;
    int g    = lane >> 2;
    int t4   = lane & 3;
    int wm   = warp >> 2;       // 0..1
    int wn   = warp & 3;        // 0..3
    int col0 = blockIdx.x * 128;

    int rcA = tid;

    float acc[4][4][4];
#pragma unroll
    for (int i = 0; i < 4; i++)
#pragma unroll
        for (int j = 0; j < 4; j++)
#pragma unroll
            for (int c = 0; c < 4; c++) acc[i][j][c] = 0.0f;

    auto issue = [&](int stage, int k0) {
        unsigned sbase = (unsigned)__cvta_generic_to_shared(smu + stage * GSTAGEU);
#pragma unroll
        for (int i = 0; i < 8; i++) {
            const int m = i >> 1;                       // compile-time plane
            int rc = (i & 1) * 256 + rcA;               // 0..511
            int r  = rc >> 2, c = rc & 3;
            const __nv_bfloat16* base =
                (m == 0) ? Ah : (m == 1) ? Al : (m == 2) ? Bh : Bl;
            int rb = (m < 2) ? row0 : col0;
            const __nv_bfloat16* src = base + (size_t)(rb + r) * DIMN + k0 + c * 8;
            unsigned dst = sbase +
                (unsigned)((m * GPLANE + r * 16 + ((c ^ ((r >> 1) & 3)) << 2)) * 4);
            asm volatile("cp.async.cg.shared.global [%0], [%1], 16;\n"
                         :: "r"(dst), "l"(src));
        }
        asm volatile("cp.async.commit_group;\n" ::: "memory");
    };

    issue(0, 0);
    issue(1, GK);

    const int NIT = DIMN / GK;   // 32
    for (int it = 0; it < NIT; ++it) {
        asm volatile("cp.async.wait_group 1;\n" ::: "memory");
        __syncthreads();
        if (it + 2 < NIT) issue((it + 2) % GSTAGES, (it + 2) * GK);
        else asm volatile("cp.async.commit_group;\n" ::: "memory");

        const unsigned* sAh = smu + (it % GSTAGES) * GSTAGEU;
        const unsigned* sAl = sAh + GPLANE;
        const unsigned* sBh = sAl + GPLANE;
        const unsigned* sBl = sBh + GPLANE;

#pragma unroll
        for (int g16 = 0; g16 < 2; g16++) {
            int p0 = g16 * 8 + t4;
            unsigned bh[4][2], bl[4][2];
#pragma unroll
            for (int nj = 0; nj < 4; nj++) {
                int Cr = wn * 32 + nj * 8 + g;
                bh[nj][0] = sBh[gsw(Cr, p0)];
                bh[nj][1] = sBh[gsw(Cr, p0 + 4)];
                bl[nj][0] = sBl[gsw(Cr, p0)];
                bl[nj][1] = sBl[gsw(Cr, p0 + 4)];
            }
#pragma unroll
            for (int mi = 0; mi < 4; mi++) {
                int Rb = wm * 64 + mi * 16;
                unsigned ah[4], al[4];
                ah[0] = sAh[gsw(Rb + g,     p0)];
                ah[1] = sAh[gsw(Rb + g + 8, p0)];
                ah[2] = sAh[gsw(Rb + g,     p0 + 4)];
                ah[3] = sAh[gsw(Rb + g + 8, p0 + 4)];
                al[0] = sAl[gsw(Rb + g,     p0)];
                al[1] = sAl[gsw(Rb + g + 8, p0)];
                al[2] = sAl[gsw(Rb + g,     p0 + 4)];
                al[3] = sAl[gsw(Rb + g + 8, p0 + 4)];
#pragma unroll
                for (int nj = 0; nj < 4; nj++) {
                    mma_bf16(acc[mi][nj], ah, bh[nj][0], bh[nj][1]);   // hi*hi
                    mma_bf16(acc[mi][nj], ah, bl[nj][0], bl[nj][1]);   // hi*lo
                    mma_bf16(acc[mi][nj], al, bh[nj][0], bh[nj][1]);   // lo*hi
                }
            }
        }
    }

    int mode = g_mask_mode;
#pragma unroll
    for (int mi = 0; mi < 4; mi++) {
#pragma unroll
        for (int h2 = 0; h2 < 2; h2++) {
            int r = row0 + wm * 64 + mi * 16 + g + 8 * h2;
            float rowscale = 1.0f;
            if (asel == 3) rowscale = mget(kpmq, (size_t)r, mode) ? 1.0f : 0.0f;
#pragma unroll
            for (int nj = 0; nj < 4; nj++) {
                int c = col0 + wn * 32 + nj * 8 + 2 * t4;
                float v0 = acc[mi][nj][2 * h2];
                float v1 = acc[mi][nj][2 * h2 + 1];
                if (asel == 0) { v0 *= 0.125f; v1 *= 0.125f; }
                if (asel == 3) {
                    Cout[(size_t)r * DIMN + c]     = v0 * rowscale;
                    Cout[(size_t)r * DIMN + c + 1] = v1 * rowscale;
                } else {
                    float* dst = (asel == 0) ? g_qp : ((asel == 1) ? g_kp : g_vp);
                    int bb = r / Nseq, ns = r - bb * Nseq;
                    int hh = c >> 6, hd = c & 63;
                    float* dp = dst + (((size_t)bb * NH + hh) * Nseq + ns) * HDIM + hd;
                    dp[0] = v0; dp[1] = v1;
                }
            }
        }
    }
}

// ---------------- distance mean -> gate coefficient -------------------------
__global__ void mean_stage1(const float* __restrict__ dist,
                            const void* __restrict__ am,
                            const void* __restrict__ kpmk)
{
    int mode = g_mask_mode;
    int b = blockIdx.y;
    size_t base = (size_t)b * NQ * NKK;
    float s = 0.0f;
    for (int i = blockIdx.x * 256 + threadIdx.x; i < NQ * NKK; i += 256 * 256) {
        int kk = i & (NKK - 1);
        if (mget(am, base + i, mode) && mget(kpmk, (size_t)b * NKK + kk, mode))
            s += dist[base + i];
    }
    __shared__ float red[256];
    red[threadIdx.x] = s;
    __syncthreads();
    for (int st = 128; st > 0; st >>= 1) {
        if (threadIdx.x < st) red[threadIdx.x] += red[threadIdx.x + st];
        __syncthreads();
    }
    if (threadIdx.x == 0) g_part[b * 256 + blockIdx.x] = red[0];
}

__global__ void mean_stage2(const float* __restrict__ galpha)
{
    int b = blockIdx.x;
    __shared__ float red[256];
    red[threadIdx.x] = g_part[b * 256 + threadIdx.x];
    __syncthreads();
    for (int st = 128; st > 0; st >>= 1) {
        if (threadIdx.x < st) red[threadIdx.x] += red[threadIdx.x + st];
        __syncthreads();
    }
    if (threadIdx.x == 0) {
        float mean = red[0] / ((float)NQ * (float)NKK + 1e-6f);
        mean = fmaxf(mean, 1e-6f);
        float a = galpha[0];
        float alpha = log1pf(__expf(a));   // softplus
        g_coef[b] = alpha / mean;
    }
}

// ---------------- precompute gate*valid ------------------------------------
__global__ void gate_kernel(const float* __restrict__ dist,
                            const void* __restrict__ am,
                            const void* __restrict__ kpmk)
{
    int mode = g_mask_mode;
    size_t i0 = ((size_t)blockIdx.x * 256 + threadIdx.x) * 4;
    const size_t per_b = (size_t)NQ * NKK;
#pragma unroll
    for (int u = 0; u < 4; u++) {
        size_t i = i0 + u;
        int b = (int)(i / per_b);
        size_t rem = i - (size_t)b * per_b;
        int kk = (int)(rem & (NKK - 1));
        bool valid = mget(am, i, mode) && mget(kpmk, (size_t)b * NKK + kk, mode);
        g_gate[i] = valid ? __expf(-g_coef[b] * dist[i]) : 0.0f;
    }
}

// ---------------- fused flash attention (tf32 mma) --------------------------
// block: 128 thr = 4 warps; q-tile 64 (warp w owns rows w*16..w*16+15);
// k-tile 64; 2 CTAs/SM so softmax of one CTA overlaps mma of the other.
#define QS_STRIDE 68
#define KS_STRIDE 68
#define VS_STRIDE 72
#define PS_STRIDE 68
#define ATTN_SMEM_UINTS (64*QS_STRIDE + 64*KS_STRIDE + 64*VS_STRIDE + 64*PS_STRIDE)

__device__ __forceinline__ float qmax(float v) {
    v = fmaxf(v, __shfl_xor_sync(0xffffffffu, v, 1));
    v = fmaxf(v, __shfl_xor_sync(0xffffffffu, v, 2));
    return v;
}
__device__ __forceinline__ float qsum(float v) {
    v += __shfl_xor_sync(0xffffffffu, v, 1);
    v += __shfl_xor_sync(0xffffffffu, v, 2);
    return v;
}

__global__ void __launch_bounds__(128, 2) attn_kernel()
{
    extern __shared__ unsigned smu[];
    unsigned* Qs = smu;                                   // [64][68]
    unsigned* Ks = Qs + 64 * QS_STRIDE;                   // [64][68]
    unsigned* Vs = Ks + 64 * KS_STRIDE;                   // [64][72]
    unsigned* Ps = Vs + 64 * VS_STRIDE;                   // [64][68]

    int tid  = threadIdx.x;
    int lane = tid & 31;
    int warp = tid >> 5;
    int g    = lane >> 2;
    int t4   = lane & 3;
    int R    = warp * 16;             // this warp's q rows within tile

    int q0 = blockIdx.x * 64;
    int h  = blockIdx.y, b = blockIdx.z;

    // load Q tile (64x64) -> Qs, tf32
    {
        const float* Qg = g_qp + ((size_t)(b * NH + h) * NQ + q0) * HDIM;
#pragma unroll
        for (int l = 0; l < 8; l++) {
            int idx4 = tid + l * 128;        // over 1024 float4s
            int row = idx4 >> 4, d4 = (idx4 & 15) * 4;
            float4 v = *(const float4*)(Qg + row * HDIM + d4);
            uint4 u = make_uint4(f2tf(v.x), f2tf(v.y), f2tf(v.z), f2tf(v.w));
            *(uint4*)(&Qs[row * QS_STRIDE + d4]) = u;
        }
    }

    float O[8][4];
    float mrow[2] = {-1e30f, -1e30f}, Z2[2] = {0.f, 0.f}, Zg2[2] = {0.f, 0.f};
#pragma unroll
    for (int nj = 0; nj < 8; nj++)
#pragma unroll
        for (int c = 0; c < 4; c++) O[nj][c] = 0.0f;

    const size_t kv_base = (size_t)(b * NH + h) * NKK * HDIM;

    for (int kbase = 0; kbase < NKK; kbase += 64) {
        __syncthreads();   // prev-tile reads done (also covers Qs stores, iter 0)
        {
            const float* Kg = g_kp + kv_base + (size_t)kbase * HDIM;
            const float* Vg = g_vp + kv_base + (size_t)kbase * HDIM;
#pragma unroll
            for (int l = 0; l < 8; l++) {
                int idx4 = tid + l * 128;    // over 1024 float4s
                int row = idx4 >> 4, d4 = (idx4 & 15) * 4;
                float4 kv = *(const float4*)(Kg + row * HDIM + d4);
                float4 vv = *(const float4*)(Vg + row * HDIM + d4);
                *(uint4*)(&Ks[row * KS_STRIDE + d4]) =
                    make_uint4(f2tf(kv.x), f2tf(kv.y), f2tf(kv.z), f2tf(kv.w));
                *(uint4*)(&Vs[row * VS_STRIDE + d4]) =
                    make_uint4(f2tf(vv.x), f2tf(vv.y), f2tf(vv.z), f2tf(vv.w));
            }
        }
        __syncthreads();

        // ---- S = Q K^T (64x64 tile; this warp: rows R..R+15) ----
        float sfr[8][4];
#pragma unroll
        for (int nj = 0; nj < 8; nj++)
#pragma unroll
            for (int c = 0; c < 4; c++) sfr[nj][c] = 0.0f;

#pragma unroll
        for (int kk = 0; kk < 8; kk++) {
            int kb = kk * 8;
            unsigned afr[4];
            afr[0] = Qs[(R + g) * QS_STRIDE + kb + t4];
            afr[1] = Qs[(R + g + 8) * QS_STRIDE + kb + t4];
            afr[2] = Qs[(R + g) * QS_STRIDE + kb + t4 + 4];
            afr[3] = Qs[(R + g + 8) * QS_STRIDE + kb + t4 + 4];
#pragma unroll
            for (int nj = 0; nj < 8; nj++) {
                unsigned bfr[2];
                bfr[0] = Ks[(nj * 8 + g) * KS_STRIDE + kb + t4];
                bfr[1] = Ks[(nj * 8 + g) * KS_STRIDE + kb + t4 + 4];
                mma_tf32(sfr[nj], afr, bfr);
            }
        }

        // ---- online softmax + gate, per half-row (rows R+g and R+g+8) ----
#pragma unroll
        for (int hf = 0; hf < 2; hf++) {
            int qrow = q0 + R + g + 8 * hf;
            const float* Gp = g_gate + ((size_t)b * NQ + qrow) * NKK + kbase;
            float Gv[16], sv[16];
            float mt = -3.0e38f;
#pragma unroll
            for (int nj = 0; nj < 8; nj++) {
                float2 gg = *(const float2*)(Gp + nj * 8 + 2 * t4);
                Gv[2 * nj] = gg.x; Gv[2 * nj + 1] = gg.y;
                float s0 = (gg.x > 0.f) ? sfr[nj][2 * hf]     : -3.0e38f;
                float s1 = (gg.y > 0.f) ? sfr[nj][2 * hf + 1] : -3.0e38f;
                sv[2 * nj] = s0; sv[2 * nj + 1] = s1;
                mt = fmaxf(mt, fmaxf(s0, s1));
            }
            mt = qmax(mt);
            float mn = fmaxf(mrow[hf], mt);
            float cs = __expf(mrow[hf] - mn);
            mrow[hf] = mn;
            float zl = 0.f, zgl = 0.f;
#pragma unroll
            for (int nj = 0; nj < 8; nj++) {
                float e0 = __expf(sv[2 * nj] - mn);
                float e1 = __expf(sv[2 * nj + 1] - mn);
                float p0 = e0 * Gv[2 * nj];
                float p1 = e1 * Gv[2 * nj + 1];
                zl += e0 + e1; zgl += p0 + p1;
                uint2 pu = make_uint2(f2tf(p0), f2tf(p1));
                *(uint2*)(&Ps[(R + g + 8 * hf) * PS_STRIDE + nj * 8 + 2 * t4]) = pu;
            }
            Z2[hf]  = Z2[hf]  * cs + zl;
            Zg2[hf] = Zg2[hf] * cs + zgl;
#pragma unroll
            for (int nj = 0; nj < 8; nj++) {
                O[nj][2 * hf]     *= cs;
                O[nj][2 * hf + 1] *= cs;
            }
        }
        __syncwarp();   // P rows are warp-private; order STS -> cross-lane LDS

        // ---- O += P @ V ----
#pragma unroll
        for (int kk = 0; kk < 8; kk++) {
            int kb = kk * 8;
            unsigned afr[4];
            afr[0] = Ps[(R + g) * PS_STRIDE + kb + t4];
            afr[1] = Ps[(R + g + 8) * PS_STRIDE + kb + t4];
            afr[2] = Ps[(R + g) * PS_STRIDE + kb + t4 + 4];
            afr[3] = Ps[(R + g + 8) * PS_STRIDE + kb + t4 + 4];
#pragma unroll
            for (int nj = 0; nj < 8; nj++) {
                unsigned bfr[2];
                bfr[0] = Vs[(kb + t4) * VS_STRIDE + nj * 8 + g];
                bfr[1] = Vs[(kb + t4 + 4) * VS_STRIDE + nj * 8 + g];
                mma_tf32(O[nj], afr, bfr);
            }
        }
    }

    // epilogue: out = O / (Zg + 1e-6*Z), write bf16 hi/lo planes directly
#pragma unroll
    for (int hf = 0; hf < 2; hf++) {
        float Zt  = qsum(Z2[hf]);
        float Zgt = qsum(Zg2[hf]);
        float inv = 1.0f / (Zgt + 1e-6f * Zt + 1e-30f);
        int qrow = q0 + R + g + 8 * hf;
        size_t obase = ((size_t)b * NQ + qrow) * (NH * HDIM) + h * HDIM;
#pragma unroll
        for (int nj = 0; nj < 8; nj++) {
            float v0 = O[nj][2 * hf] * inv;
            float v1 = O[nj][2 * hf + 1] * inv;
            __nv_bfloat16 h0 = __float2bfloat16(v0);
            __nv_bfloat16 h1 = __float2bfloat16(v1);
            __nv_bfloat16 l0 = __float2bfloat16(v0 - __bfloat162float(h0));
            __nv_bfloat16 l1 = __float2bfloat16(v1 - __bfloat162float(h1));
            size_t off = obase + nj * 8 + 2 * t4;
            *(__nv_bfloat162*)(g_ah + off) = __nv_bfloat162(h0, h1);
            *(__nv_bfloat162*)(g_al + off) = __nv_bfloat162(l0, l1);
        }
    }
}

// ---------------- launch -----------------------------------------------------
extern "C" void kernel_launch(void* const* d_in, const int* in_sizes, int n_in,
                              void* d_out, int out_size)
{
    const float* q     = (const float*)d_in[0];
    const float* k     = (const float*)d_in[1];
    const float* v     = (const float*)d_in[2];
    const float* dist  = (const float*)d_in[3];
    const void*  amask = d_in[4];
    const void*  kpmq  = d_in[5];
    const void*  kpmk  = d_in[6];
    const float* ga    = (const float*)d_in[11];
    float* out = (float*)d_out;

    const int attn_smem = ATTN_SMEM_UINTS * (int)sizeof(unsigned);  // ~69 KB
    const int gemm_smem = GSMEMU * (int)sizeof(unsigned);           // 96 KB
    cudaFuncSetAttribute(attn_kernel,
                         cudaFuncAttributeMaxDynamicSharedMemorySize, attn_smem);
    cudaFuncSetAttribute(gemm_bf16x3,
                         cudaFuncAttributeMaxDynamicSharedMemorySize, gemm_smem);

    detect_kernel<<<1, 256>>>((const unsigned int*)amask);

    // all fp32 -> bf16 hi/lo conversions in a single launch
    convert_all<<<7168, 256>>>(q, k, v,
                               (const float*)d_in[7], (const float*)d_in[8],
                               (const float*)d_in[9], (const float*)d_in[10]);

    // fused Q+K+V projection GEMMs (one launch, 640 CTAs)
    gemm_bf16x3<<<dim3(8, 80), 256, gemm_smem>>>(nullptr, -1, nullptr);

    mean_stage1<<<dim3(256, BB), 256>>>(dist, amask, kpmk);
    mean_stage2<<<BB, 256>>>(ga);
    gate_kernel<<<(BB * NQ * NKK) / (256 * 4), 256>>>(dist, amask, kpmk);

    attn_kernel<<<dim3(NQ / 64, NH, BB), 128, attn_smem>>>();

    gemm_bf16x3<<<dim3(8, 16), 256, gemm_smem>>>(out, 3, kpmq);
}